// round 14
// baseline (speedup 1.0000x reference)
#include <cuda_runtime.h>
#include <math.h>

#define BS   64
#define CIN  256
#define II   1024
#define J    10
#define D    32
#define OD   320
#define NP   4
#define TI   256     // II / NP

typedef unsigned long long ull;

// ---------------- scratch (static device globals; no allocation) ----------------
__device__ float g_xsum [BS*CIN];
__device__ float g_ypart[BS*NP*J*CIN];
__device__ float g_cpart[BS*NP*J];

// ---------------- f32x2 helpers ----------------
static __device__ __forceinline__ void ffma2(ull &d, ull a, ull b) {
    asm("fma.rn.f32x2 %0, %1, %2, %0;" : "+l"(d) : "l"(a), "l"(b));
}
static __device__ __forceinline__ ull add2(ull a, ull b) {
    ull r; asm("add.rn.f32x2 %0, %1, %2;" : "=l"(r) : "l"(a), "l"(b)); return r;
}
static __device__ __forceinline__ ull pack2(float lo, float hi) {
    ull r; asm("mov.b64 %0, {%1, %2};" : "=l"(r) : "f"(lo), "f"(hi)); return r;
}
static __device__ __forceinline__ ull dup2(float x) {
    unsigned int u = __float_as_uint(x);
    return ((ull)u << 32) | (ull)u;
}
static __device__ __forceinline__ float lo2(ull v) {
    return __uint_as_float((unsigned int)(v & 0xffffffffu));
}
static __device__ __forceinline__ float hi2(ull v) {
    return __uint_as_float((unsigned int)(v >> 32));
}

// ---------------- K1: xsum[b,c] = sum_i x[b,c,i] ----------------
__global__ void k_xsum(const float* __restrict__ x) {
    int warp = (blockIdx.x * blockDim.x + threadIdx.x) >> 5;
    int lane = threadIdx.x & 31;
    if (warp >= BS * CIN) return;
    const float4* row = (const float4*)(x + (size_t)warp * II);
    float s = 0.0f;
    #pragma unroll
    for (int k = 0; k < II / 128; k++) {
        float4 v = row[k * 32 + lane];
        s += v.x + v.y + v.z + v.w;
    }
    #pragma unroll
    for (int off = 16; off; off >>= 1) s += __shfl_xor_sync(0xffffffffu, s, off);
    if (lane == 0) g_xsum[warp] = s;
}

// ---------------- K_pass<ITER>: in-block sv + logits + softmax + y ------------
// grid (NP, BS), 256 threads.
// region1 (32KB) timeline: [usm_dup 20KB + sv scratch] -> psm 22.5KB -> xsm 32KB
// region2 (10KB) timeline: ysm (sv, ITER=2) -> cssm (softmax on)
template<int ITER>
__global__ void __launch_bounds__(256) k_pass(const float* __restrict__ x,
                                              const float* __restrict__ W,
                                              const float* __restrict__ Wb) {
    __shared__ __align__(16) char  r1[32768];
    __shared__ __align__(16) float r2[J * CIN];
    __shared__ float vbs[J];
    __shared__ float csum2[J + 2];

    ull*   usm  = (ull*)r1;                       // [j*256 + c], dup2
    ull*   psm  = (ull*)r1;                       // [(cg*32+ig)*11 + j]
    float* xsm  = (float*)r1;                     // phase B staging (R2 swizzle)
    float* y1sm = (float*)(r1 + 20480);           // 256
    float* ssm1 = (float*)(r1 + 21504);           // 320
    float* ssm2 = (float*)(r1 + 22784);           // 320
    float* vsum = (float*)(r1 + 24064);           // 320
    float* ysm  = r2;
    float* cssm = r2;

    int tile = blockIdx.x, b = blockIdx.y, t = threadIdx.x;
    int w = t >> 5, l = t & 31;
    const float* xb = x + (size_t)b * CIN * II;
    int i0 = tile * TI;

    // ======== sv: y vectors ========
    y1sm[t] = g_xsum[b * CIN + t] * (1.0f / (float)J);
    if (ITER == 2) {
        #pragma unroll
        for (int j = 0; j < J; j++) {
            const float* yp = g_ypart + (((size_t)b * NP) * J + j) * CIN + t;
            ysm[j * CIN + t] = (yp[0] + yp[(size_t)J * CIN])
                             + (yp[2 * (size_t)J * CIN] + yp[3 * (size_t)J * CIN]);
        }
        if (t < J) {
            const float* cp = g_cpart + (b * NP) * J + t;
            csum2[t] = (cp[0] + cp[J]) + (cp[2 * J] + cp[3 * J]);
        }
    }
    __syncthreads();

    // ---- s-stage: s1 (and s2) via warp dots, packed shfl reduce ----
    const float c1 = (float)II / (float)J;
    for (int o = w; o < OD; o += 8) {
        int j = o >> 5;
        const float4* wr = (const float4*)(W + (size_t)o * CIN);
        float4 w0 = wr[l], w1 = wr[l + 32];
        const float4* yv = (const float4*)y1sm;
        float4 ya = yv[l], yb = yv[l + 32];
        float d1 = w0.x*ya.x + w0.y*ya.y + w0.z*ya.z + w0.w*ya.w
                 + w1.x*yb.x + w1.y*yb.y + w1.z*yb.z + w1.w*yb.w;
        float d2 = 0.0f;
        if (ITER == 2) {
            const float4* zv = (const float4*)(ysm + j * CIN);
            float4 za = zv[l], zb = zv[l + 32];
            d2 = w0.x*za.x + w0.y*za.y + w0.z*za.z + w0.w*za.w
               + w1.x*zb.x + w1.y*zb.y + w1.z*zb.z + w1.w*zb.w;
        }
        ull p = pack2(d1, d2);
        #pragma unroll
        for (int o2 = 16; o2; o2 >>= 1) p = add2(p, __shfl_xor_sync(0xffffffffu, p, o2));
        if (l == 0) {
            float wbv = Wb[o];
            ssm1[o] = lo2(p) + c1 * wbv;
            if (ITER == 2) ssm2[o] = hi2(p) + csum2[j] * wbv;
        }
    }
    __syncthreads();

    // ---- squash -> vsum = v1 (+ v2), vbs[j] = vsum . Wb_j ----
    for (int j = w; j < J; j += 8) {
        int o = j * D + l;
        float s1 = ssm1[o];
        float s2 = (ITER == 2) ? ssm2[o] : 0.0f;
        ull n = pack2(s1 * s1, s2 * s2);
        #pragma unroll
        for (int o2 = 16; o2; o2 >>= 1) n = add2(n, __shfl_xor_sync(0xffffffffu, n, o2));
        float n1 = lo2(n), n2 = hi2(n);
        float v = s1 * (n1 / ((1.0f + n1) * sqrtf(n1)));
        if (ITER == 2) v += s2 * (n2 / ((1.0f + n2) * sqrtf(n2)));
        vsum[o] = v;
        float pv = v * Wb[o];
        #pragma unroll
        for (int o2 = 16; o2; o2 >>= 1) pv += __shfl_xor_sync(0xffffffffu, pv, o2);
        if (l == 0) vbs[j] = pv;
    }
    __syncwarp();

    // ---- u-stage: u[j][c] = sum_d vsum[j,d]*W[jD+d,c] -> usm dup2 ----
    for (int j = w; j < J; j += 8) {
        float4 ac0 = make_float4(0,0,0,0), ac1 = make_float4(0,0,0,0);
        #pragma unroll
        for (int d = 0; d < D; d++) {
            float vd = vsum[j * D + d];
            const float4* wr = (const float4*)(W + (size_t)(j * D + d) * CIN);
            float4 wa = wr[l], wb2 = wr[l + 32];
            ac0.x = fmaf(vd, wa.x,  ac0.x); ac0.y = fmaf(vd, wa.y,  ac0.y);
            ac0.z = fmaf(vd, wa.z,  ac0.z); ac0.w = fmaf(vd, wa.w,  ac0.w);
            ac1.x = fmaf(vd, wb2.x, ac1.x); ac1.y = fmaf(vd, wb2.y, ac1.y);
            ac1.z = fmaf(vd, wb2.z, ac1.z); ac1.w = fmaf(vd, wb2.w, ac1.w);
        }
        int ca = 4 * l, cb = 128 + 4 * l;
        usm[j * 256 + ca + 0] = dup2(ac0.x); usm[j * 256 + ca + 1] = dup2(ac0.y);
        usm[j * 256 + ca + 2] = dup2(ac0.z); usm[j * 256 + ca + 3] = dup2(ac0.w);
        usm[j * 256 + cb + 0] = dup2(ac1.x); usm[j * 256 + cb + 1] = dup2(ac1.y);
        usm[j * 256 + cb + 2] = dup2(ac1.z); usm[j * 256 + cb + 3] = dup2(ac1.w);
    }
    __syncthreads();

    // ======== phase A: logits. thread = (cg=w: 32 c, ig=l: 8 i) ========
    ull a0[J], a1[J], a2[J], a3[J];
    #pragma unroll
    for (int j = 0; j < J; j++) { a0[j] = 0ull; a1[j] = 0ull; a2[j] = 0ull; a3[j] = 0ull; }
    {
        const float* xp = xb + (size_t)(w * 32) * II + i0 + l * 8;
        #pragma unroll 2
        for (int cc = 0; cc < 32; cc++) {
            const float* xc = xp + (size_t)cc * II;
            ulonglong2 xA = *(const ulonglong2*)xc;        // i: 8l+0..3
            ulonglong2 xB = *(const ulonglong2*)(xc + 4);  // i: 8l+4..7
            const ull* up = usm + w * 32 + cc;
            #pragma unroll
            for (int j = 0; j < J; j++) {
                ull ud = up[j * 256];                      // broadcast
                ffma2(a0[j], ud, xA.x); ffma2(a1[j], ud, xA.y);
                ffma2(a2[j], ud, xB.x); ffma2(a3[j], ud, xB.y);
            }
        }
    }

    // ---- combine 8 c-groups + softmax, 4 rounds (i-pair r) ----
    #pragma unroll
    for (int r = 0; r < 4; r++) {
        __syncthreads();   // round 0: also guards psm overwrite of usm
        #pragma unroll
        for (int j = 0; j < J; j++) {
            ull v = (r == 0) ? a0[j] : (r == 1) ? a1[j] : (r == 2) ? a2[j] : a3[j];
            psm[(w * 32 + l) * 11 + j] = v;
        }
        __syncthreads();
        if (t < 64) {
            int ig = t >> 1, h = t & 1;
            int i = ig * 8 + r * 2 + h;
            float lg[J];
            #pragma unroll
            for (int j = 0; j < J; j++) {
                float s = vbs[j];
                #pragma unroll
                for (int g = 0; g < 8; g++)
                    s += ((const float*)&psm[(g * 32 + ig) * 11 + j])[h];
                lg[j] = s;
            }
            float m = lg[0];
            #pragma unroll
            for (int j = 1; j < J; j++) m = fmaxf(m, lg[j]);
            float ssum = 0.0f;
            #pragma unroll
            for (int j = 0; j < J; j++) { lg[j] = __expf(lg[j] - m); ssum += lg[j]; }
            float rr = 1.0f / ssum;
            #pragma unroll
            for (int j = 0; j < J; j++) cssm[j * TI + i] = lg[j] * rr;
        }
    }
    __syncthreads();

    // ---- csum partials ----
    for (int j = w; j < J; j += 8) {
        const float4* p4 = (const float4*)(cssm + j * TI);
        float4 A = p4[l * 2], B4 = p4[l * 2 + 1];
        float sc = A.x + A.y + A.z + A.w + B4.x + B4.y + B4.z + B4.w;
        #pragma unroll
        for (int o2 = 16; o2; o2 >>= 1) sc += __shfl_xor_sync(0xffffffffu, sc, o2);
        if (l == 0) g_cpart[(b * NP + tile) * J + j] = sc;
    }

    // ======== phase B: ypart[j][c=t] (R2-proven staged body) ========
    ull y0[J], y1[J];
    #pragma unroll
    for (int j = 0; j < J; j++) { y0[j] = 0ull; y1[j] = 0ull; }
    #pragma unroll 1
    for (int ch = 0; ch < TI / 32; ch++) {
        __syncthreads();
        #pragma unroll
        for (int sw = 0; sw < 8; sw++) {
            int row = sw * 32 + (t >> 3);
            int q   = t & 7;
            float4 v = *(const float4*)(xb + (size_t)row * II + i0 + ch * 32 + q * 4);
            int sidx = row * 32 + ((q ^ (row & 7)) << 2);
            *(float4*)(xsm + sidx) = v;
        }
        __syncthreads();
        #pragma unroll
        for (int g = 0; g < 8; g++) {
            int sidx = t * 32 + ((g ^ (t & 7)) << 2);
            float4 xv = *(const float4*)(xsm + sidx);
            ull x01 = pack2(xv.x, xv.y), x23 = pack2(xv.z, xv.w);
            int ii = ch * 32 + g * 4;
            #pragma unroll
            for (int j = 0; j < J; j++) {
                ulonglong2 cv = *(const ulonglong2*)(cssm + j * TI + ii);
                ffma2(y0[j], cv.x, x01);
                ffma2(y1[j], cv.y, x23);
            }
        }
    }
    #pragma unroll
    for (int j = 0; j < J; j++)
        g_ypart[(((size_t)b * NP + tile) * J + j) * CIN + t] =
            (lo2(y0[j]) + hi2(y0[j])) + (lo2(y1[j]) + hi2(y1[j]));
}

// ---------------- K_fin: final sv -> out (R2 k_sv mode-2 shape) --------------
__global__ void __launch_bounds__(256) k_fin(const float* __restrict__ W,
                                             const float* __restrict__ Wb,
                                             float* __restrict__ out) {
    int j = blockIdx.x, b = blockIdx.y, t = threadIdx.x;
    int wid = t >> 5, lane = t & 31;
    __shared__ __align__(16) float ysm[CIN];
    __shared__ float ssm[D];
    __shared__ float csum_s;

    const float* yp = g_ypart + (((size_t)b * NP) * J + j) * CIN + t;
    ysm[t] = (yp[0] + yp[(size_t)J * CIN])
           + (yp[2 * (size_t)J * CIN] + yp[3 * (size_t)J * CIN]);
    if (t == 0) {
        const float* cp = g_cpart + (b * NP) * J + j;
        csum_s = (cp[0] + cp[J]) + (cp[2 * J] + cp[3 * J]);
    }
    __syncthreads();
    float csum = csum_s;

    for (int d = wid; d < D; d += 8) {
        const float4* wr = (const float4*)(W + (size_t)(j * D + d) * CIN);
        const float4* yr = (const float4*)ysm;
        float4 w0 = wr[lane * 2], w1 = wr[lane * 2 + 1];
        float4 y0 = yr[lane * 2], y1 = yr[lane * 2 + 1];
        float a = w0.x*y0.x + w0.y*y0.y + w0.z*y0.z + w0.w*y0.w
                + w1.x*y1.x + w1.y*y1.y + w1.z*y1.z + w1.w*y1.w;
        #pragma unroll
        for (int off = 16; off; off >>= 1) a += __shfl_xor_sync(0xffffffffu, a, off);
        if (lane == 0) ssm[d] = a + csum * Wb[j * D + d];
    }
    __syncthreads();

    if (wid == 0) {
        float s = ssm[lane];
        float ns = s * s;
        #pragma unroll
        for (int off = 16; off; off >>= 1) ns += __shfl_xor_sync(0xffffffffu, ns, off);
        float coef = ns / ((1.0f + ns) * sqrtf(ns));
        out[(b * J + j) * D + lane] = s * coef;
    }
}

// ---------------- launch ----------------
extern "C" void kernel_launch(void* const* d_in, const int* in_sizes, int n_in,
                              void* d_out, int out_size) {
    const float* x  = (const float*)d_in[0];   // [64,256,32,32]
    const float* W  = (const float*)d_in[1];   // [320,256]
    const float* Wb = (const float*)d_in[2];   // [320]
    float* out = (float*)d_out;                // [64,10,32]

    k_xsum  <<<BS * CIN / 8, 256>>>(x);
    k_pass<1><<<dim3(NP, BS), 256>>>(x, W, Wb);   // sv1 in-block -> iter2 pass
    k_pass<2><<<dim3(NP, BS), 256>>>(x, W, Wb);   // sv1+sv2 in-block -> iter3 pass
    k_fin   <<<dim3(J, BS), 256>>>(W, Wb, out);   // final squash -> out
}

// round 17
// speedup vs baseline: 1.3224x; 1.3224x over previous
#include <cuda_runtime.h>
#include <math.h>

#define BS   64
#define CIN  256
#define II   1024
#define J    10
#define D    32
#define OD   320
#define NTILE 4
#define TILE_I 256    // II / NTILE

typedef unsigned long long ull;

// ---------------- scratch (static device globals; no allocation) ----------------
__device__ float g_u    [BS*J*CIN];          // accumulated u_j = W_j^T v_j
__device__ float g_vb   [BS*J];
__device__ float g_ypart[BS*NTILE*J*CIN];
__device__ float g_cpart[BS*NTILE*J];

// ---------------- f32x2 helpers ----------------
static __device__ __forceinline__ void ffma2(ull &d, ull a, ull b) {
    asm("fma.rn.f32x2 %0, %1, %2, %0;" : "+l"(d) : "l"(a), "l"(b));
}
static __device__ __forceinline__ ull pack2(float lo, float hi) {
    ull r; asm("mov.b64 %0, {%1, %2};" : "=l"(r) : "f"(lo), "f"(hi)); return r;
}
static __device__ __forceinline__ float lo2(ull v) {
    return __uint_as_float((unsigned int)(v & 0xffffffffu));
}
static __device__ __forceinline__ float hi2(ull v) {
    return __uint_as_float((unsigned int)(v >> 32));
}

// ---------------- K_head: per-batch xsum + sv1 (u1, vb1) ----------------------
// grid (BS), 1024 threads. Reads x[b] once; W once per block.
__global__ void __launch_bounds__(1024) k_head(const float* __restrict__ x,
                                               const float* __restrict__ W,
                                               const float* __restrict__ Wb) {
    int b = blockIdx.x, t = threadIdx.x;
    int w = t >> 5, l = t & 31;
    __shared__ __align__(16) float ysm[CIN];   // xsum / J
    __shared__ float ssm[OD];
    __shared__ float vsm[OD];

    // ---- xsum: warp w owns rows [8w, 8w+8); coalesced float4 ----
    #pragma unroll
    for (int rr = 0; rr < 8; rr++) {
        int r = w * 8 + rr;
        const float4* row = (const float4*)(x + ((size_t)b * CIN + r) * II);
        float s = 0.0f;
        #pragma unroll
        for (int k = 0; k < 8; k++) {
            float4 v = row[k * 32 + l];
            s += v.x + v.y + v.z + v.w;
        }
        #pragma unroll
        for (int o = 16; o; o >>= 1) s += __shfl_xor_sync(0xffffffffu, s, o);
        if (l == 0) ysm[r] = s * (1.0f / (float)J);
    }
    __syncthreads();

    // ---- s[o] = W[o,:].ysm + (II/J)*Wb[o]; 32 warps x 10 dots ----
    const float c1 = (float)II / (float)J;
    for (int o = w; o < OD; o += 32) {
        const float4* wr = (const float4*)(W + (size_t)o * CIN);
        const float4* yr = (const float4*)ysm;
        float4 w0 = wr[l * 2], w1 = wr[l * 2 + 1];
        float4 y0 = yr[l * 2], y1 = yr[l * 2 + 1];
        float a = w0.x*y0.x + w0.y*y0.y + w0.z*y0.z + w0.w*y0.w
                + w1.x*y1.x + w1.y*y1.y + w1.z*y1.z + w1.w*y1.w;
        #pragma unroll
        for (int o2 = 16; o2; o2 >>= 1) a += __shfl_xor_sync(0xffffffffu, a, o2);
        if (l == 0) ssm[o] = a + c1 * Wb[o];
    }
    __syncthreads();

    // ---- squash: warp j (< J) ----
    if (w < J) {
        int o = w * D + l;
        float s = ssm[o];
        float ns = s * s;
        #pragma unroll
        for (int o2 = 16; o2; o2 >>= 1) ns += __shfl_xor_sync(0xffffffffu, ns, o2);
        float coef = ns / ((1.0f + ns) * sqrtf(ns));
        float v = s * coef;
        vsm[o] = v;
        float pv = v * Wb[o];
        #pragma unroll
        for (int o2 = 16; o2; o2 >>= 1) pv += __shfl_xor_sync(0xffffffffu, pv, o2);
        if (l == 0) g_vb[b * J + w] = pv;
    }
    __syncthreads();

    // ---- u1[j][c] = sum_d v[j,d] * W[jD+d,c]; thread = (q=t>>8, c=t&255) ----
    int c = t & 255, q = t >> 8;
    #pragma unroll
    for (int p = 0; p < 3; p++) {
        int j = q + 4 * p;
        if (j < J) {
            float a = 0.0f;
            #pragma unroll
            for (int d = 0; d < D; d++)
                a = fmaf(vsm[j * D + d], W[(size_t)(j * D + d) * CIN + c], a);
            g_u[((size_t)b * J + j) * CIN + c] = a;
        }
    }
}

// ---------------- K_sv (R2-proven, mode1 only): per (b,j) block ---------------
__global__ void __launch_bounds__(256) k_sv(const float* __restrict__ W,
                                            const float* __restrict__ Wb) {
    int j = blockIdx.x, b = blockIdx.y, t = threadIdx.x;
    int wid = t >> 5, lane = t & 31;
    __shared__ __align__(16) float ysm[CIN];
    __shared__ float ssm[D];
    __shared__ float vsm[D];
    __shared__ float csum_s;

    float yv = 0.0f;
    #pragma unroll
    for (int p = 0; p < NTILE; p++)
        yv += g_ypart[(((size_t)b * NTILE + p) * J + j) * CIN + t];
    if (t == 0) {
        float a = 0.0f;
        #pragma unroll
        for (int p = 0; p < NTILE; p++) a += g_cpart[(b * NTILE + p) * J + j];
        csum_s = a;
    }
    ysm[t] = yv;
    __syncthreads();
    float csum = csum_s;

    for (int d = wid; d < D; d += 8) {
        const float4* wr = (const float4*)(W + (size_t)(j * D + d) * CIN);
        const float4* yr = (const float4*)ysm;
        float4 w0 = wr[lane * 2], w1 = wr[lane * 2 + 1];
        float4 y0 = yr[lane * 2], y1 = yr[lane * 2 + 1];
        float a = w0.x * y0.x + w0.y * y0.y + w0.z * y0.z + w0.w * y0.w
                + w1.x * y1.x + w1.y * y1.y + w1.z * y1.z + w1.w * y1.w;
        #pragma unroll
        for (int off = 16; off; off >>= 1) a += __shfl_xor_sync(0xffffffffu, a, off);
        if (lane == 0) ssm[d] = a + csum * Wb[j * D + d];
    }
    __syncthreads();

    if (wid == 0) {
        float s = ssm[lane];
        float ns = s * s;
        #pragma unroll
        for (int off = 16; off; off >>= 1) ns += __shfl_xor_sync(0xffffffffu, ns, off);
        float coef = ns / ((1.0f + ns) * sqrtf(ns));
        float v = s * coef;
        vsm[lane] = v;
        float pv = v * Wb[j * D + lane];
        #pragma unroll
        for (int off = 16; off; off >>= 1) pv += __shfl_xor_sync(0xffffffffu, pv, off);
        if (lane == 0) g_vb[b * J + j] += pv;
    }
    __syncthreads();

    {
        float a = 0.0f;
        #pragma unroll
        for (int d = 0; d < D; d++)
            a = fmaf(vsm[d], W[(size_t)(j * D + d) * CIN + t], a);
        size_t idx = ((size_t)b * J + j) * CIN + t;
        g_u[idx] = g_u[idx] + a;
    }
}

// ---------------- K_pass (R2-proven): logits -> softmax -> ypart, cpart -------
__global__ void __launch_bounds__(256) k_pass(const float* __restrict__ x) {
    __shared__ __align__(16) ull   usm[J * (CIN / 2)];     // u packed c-pairs, 10KB
    __shared__ float vbs[J];
    __shared__ __align__(16) float cssm[J * TILE_I];       // coeffs [j][i], 10KB
    __shared__ __align__(16) float xsm[CIN * 32];          // 32-i chunk, swizzled, 32KB

    int b = blockIdx.y, tile = blockIdx.x, t = threadIdx.x;
    int wid = t >> 5, lane = t & 31;

    const ull* up = (const ull*)(g_u + (size_t)b * J * CIN);
    for (int idx = t; idx < J * CIN / 2; idx += 256) usm[idx] = up[idx];
    if (t < J) vbs[t] = g_vb[b * J + t];
    __syncthreads();

    const float* xb = x + (size_t)b * CIN * II;
    int i0 = tile * TILE_I;

    // ---- phase A: logit[j] = u_j . x[:, i] + vb_j ; i = i0 + t ----
    {
        const float* xi = xb + i0 + t;
        ull acc[J];
        #pragma unroll
        for (int j = 0; j < J; j++) acc[j] = 0ull;
        #pragma unroll 2
        for (int cq = 0; cq < CIN / 4; cq++) {
            float x0 = __ldg(xi + (size_t)(4 * cq + 0) * II);
            float x1 = __ldg(xi + (size_t)(4 * cq + 1) * II);
            float x2 = __ldg(xi + (size_t)(4 * cq + 2) * II);
            float x3 = __ldg(xi + (size_t)(4 * cq + 3) * II);
            ull x01 = pack2(x0, x1), x23 = pack2(x2, x3);
            #pragma unroll
            for (int j = 0; j < J; j++) {
                ulonglong2 u4 = *(const ulonglong2*)(usm + j * (CIN / 2) + cq * 2);
                ffma2(acc[j], u4.x, x01);
                ffma2(acc[j], u4.y, x23);
            }
        }
        float lg[J];
        #pragma unroll
        for (int j = 0; j < J; j++) lg[j] = lo2(acc[j]) + hi2(acc[j]) + vbs[j];
        float m = lg[0];
        #pragma unroll
        for (int j = 1; j < J; j++) m = fmaxf(m, lg[j]);
        float s = 0.0f;
        #pragma unroll
        for (int j = 0; j < J; j++) { lg[j] = __expf(lg[j] - m); s += lg[j]; }
        float r = 1.0f / s;
        #pragma unroll
        for (int j = 0; j < J; j++) cssm[j * TILE_I + t] = lg[j] * r;
    }
    __syncthreads();

    // ---- csum partials ----
    for (int j = wid; j < J; j += 8) {
        const float4* p = (const float4*)(cssm + j * TILE_I);
        float4 a = p[lane * 2], b4 = p[lane * 2 + 1];
        float sc = a.x + a.y + a.z + a.w + b4.x + b4.y + b4.z + b4.w;
        #pragma unroll
        for (int off = 16; off; off >>= 1) sc += __shfl_xor_sync(0xffffffffu, sc, off);
        if (lane == 0) g_cpart[(b * NTILE + tile) * J + j] = sc;
    }

    // ---- phase B: ypart[j][c=t] over 32-i staged swizzled chunks ----
    ull yacc[J][2];
    #pragma unroll
    for (int j = 0; j < J; j++) { yacc[j][0] = 0ull; yacc[j][1] = 0ull; }

    #pragma unroll 1
    for (int ch = 0; ch < TILE_I / 32; ch++) {
        __syncthreads();
        #pragma unroll
        for (int sw = 0; sw < 8; sw++) {
            int row = sw * 32 + (t >> 3);
            int q   = t & 7;
            float4 v = *(const float4*)(xb + (size_t)row * II + i0 + ch * 32 + q * 4);
            int sidx = row * 32 + ((q ^ (row & 7)) << 2);
            *(float4*)(xsm + sidx) = v;
        }
        __syncthreads();
        #pragma unroll
        for (int g = 0; g < 8; g++) {
            int sidx = t * 32 + ((g ^ (t & 7)) << 2);
            float4 xv = *(const float4*)(xsm + sidx);
            ull x01 = pack2(xv.x, xv.y), x23 = pack2(xv.z, xv.w);
            int ii = ch * 32 + g * 4;
            #pragma unroll
            for (int j = 0; j < J; j++) {
                float4 cv = *(const float4*)(cssm + j * TILE_I + ii);  // uniform
                ffma2(yacc[j][0], pack2(cv.x, cv.y), x01);
                ffma2(yacc[j][1], pack2(cv.z, cv.w), x23);
            }
        }
    }
    #pragma unroll
    for (int j = 0; j < J; j++)
        g_ypart[(((size_t)b * NTILE + tile) * J + j) * CIN + t] =
            (lo2(yacc[j][0]) + hi2(yacc[j][0])) + (lo2(yacc[j][1]) + hi2(yacc[j][1]));
}

// ---------------- K_fin (R14-proven, 7.6us): final sv -> out ------------------
__global__ void __launch_bounds__(256) k_fin(const float* __restrict__ W,
                                             const float* __restrict__ Wb,
                                             float* __restrict__ out) {
    int j = blockIdx.x, b = blockIdx.y, t = threadIdx.x;
    int wid = t >> 5, lane = t & 31;
    __shared__ __align__(16) float ysm[CIN];
    __shared__ float ssm[D];
    __shared__ float csum_s;

    const float* yp = g_ypart + (((size_t)b * NTILE) * J + j) * CIN + t;
    ysm[t] = (yp[0] + yp[(size_t)J * CIN])
           + (yp[2 * (size_t)J * CIN] + yp[3 * (size_t)J * CIN]);
    if (t == 0) {
        const float* cp = g_cpart + (b * NTILE) * J + j;
        csum_s = (cp[0] + cp[J]) + (cp[2 * J] + cp[3 * J]);
    }
    __syncthreads();
    float csum = csum_s;

    for (int d = wid; d < D; d += 8) {
        const float4* wr = (const float4*)(W + (size_t)(j * D + d) * CIN);
        const float4* yr = (const float4*)ysm;
        float4 w0 = wr[lane * 2], w1 = wr[lane * 2 + 1];
        float4 y0 = yr[lane * 2], y1 = yr[lane * 2 + 1];
        float a = w0.x*y0.x + w0.y*y0.y + w0.z*y0.z + w0.w*y0.w
                + w1.x*y1.x + w1.y*y1.y + w1.z*y1.z + w1.w*y1.w;
        #pragma unroll
        for (int off = 16; off; off >>= 1) a += __shfl_xor_sync(0xffffffffu, a, off);
        if (lane == 0) ssm[d] = a + csum * Wb[j * D + d];
    }
    __syncthreads();

    if (wid == 0) {
        float s = ssm[lane];
        float ns = s * s;
        #pragma unroll
        for (int off = 16; off; off >>= 1) ns += __shfl_xor_sync(0xffffffffu, ns, off);
        float coef = ns / ((1.0f + ns) * sqrtf(ns));
        out[(b * J + j) * D + lane] = s * coef;
    }
}

// ---------------- launch ----------------
extern "C" void kernel_launch(void* const* d_in, const int* in_sizes, int n_in,
                              void* d_out, int out_size) {
    const float* x  = (const float*)d_in[0];   // [64,256,32,32]
    const float* W  = (const float*)d_in[1];   // [320,256]
    const float* Wb = (const float*)d_in[2];   // [320]
    float* out = (float*)d_out;                // [64,10,32]

    k_head<<<BS, 1024>>>(x, W, Wb);            // xsum + sv1 fused (u1, vb1)
    k_pass<<<dim3(NTILE, BS), 256>>>(x);       // iter2 logits+softmax+y
    k_sv  <<<dim3(J, BS), 256>>>(W, Wb);       // iter2: v2, u+=, vb+=
    k_pass<<<dim3(NTILE, BS), 256>>>(x);       // iter3 logits+softmax+y
    k_fin <<<dim3(J, BS), 256>>>(W, Wb, out);  // iter3: final v -> out
}